// round 3
// baseline (speedup 1.0000x reference)
#include <cuda_runtime.h>
#include <cuda_bf16.h>
#include <math.h>

#define NN    4096
#define CC    512
#define HH    8
#define COH   64
#define EE    131072
#define QKVW  1536

// ---------------- scratch ----------------
// float scratch layout (element offsets)
#define S_XL   0L
#define S_XR   (S_XL  + (long)NN*CC)
#define S_HB   (S_XR  + (long)NN*CC)
#define S_X1   (S_HB  + (long)NN*CC)
#define S_QKV  (S_X1  + (long)NN*CC)
#define S_ATT  (S_QKV + (long)NN*3*CC)
#define S_X2   (S_ATT + (long)NN*CC)
#define S_FFN  (S_X2  + (long)NN*CC)
#define S_TOT  (S_FFN + (long)NN*4*CC)

__device__ float g_scratch[S_TOT];

// int scratch
#define I_DEG  0
#define I_OFF  4096
#define I_POS  (I_OFF + 4097)
#define I_ESRC (I_POS + 4096)
__device__ int g_ints[I_ESRC + EE];

// ---------------- CSR build (edge_index is int32: [2, E] row-major) ----------------
__global__ void k_zero_deg() {
    int i = blockIdx.x * blockDim.x + threadIdx.x;
    if (i < NN) g_ints[I_DEG + i] = 0;
}

__global__ void k_count(const int* __restrict__ ei) {
    int e = blockIdx.x * blockDim.x + threadIdx.x;
    if (e < EE) {
        int d = ei[EE + e] & (NN - 1);
        atomicAdd(&g_ints[I_DEG + d], 1);
    }
}

__global__ void k_scan() {
    __shared__ int ws[32];
    int t = threadIdx.x;                 // 1024 threads, 4 elems each
    int v[4]; int tot = 0;
#pragma unroll
    for (int j = 0; j < 4; j++) { v[j] = g_ints[I_DEG + t*4 + j]; tot += v[j]; }
    int lane = t & 31, wid = t >> 5;
    int sc = tot;
#pragma unroll
    for (int o = 1; o < 32; o <<= 1) {
        int y = __shfl_up_sync(0xffffffffu, sc, o);
        if (lane >= o) sc += y;
    }
    if (lane == 31) ws[wid] = sc;
    __syncthreads();
    if (wid == 0) {
        int z = ws[lane];
#pragma unroll
        for (int o = 1; o < 32; o <<= 1) {
            int y = __shfl_up_sync(0xffffffffu, z, o);
            if (lane >= o) z += y;
        }
        ws[lane] = z;
    }
    __syncthreads();
    int excl = sc - tot + (wid ? ws[wid - 1] : 0);
    int run = excl;
#pragma unroll
    for (int j = 0; j < 4; j++) {
        g_ints[I_OFF + t*4 + j] = run;
        g_ints[I_POS + t*4 + j] = run;
        run += v[j];
    }
    if (t == 1023) g_ints[I_OFF + 4096] = run;
}

__global__ void k_scatter(const int* __restrict__ ei) {
    int e = blockIdx.x * blockDim.x + threadIdx.x;
    if (e < EE) {
        int d = ei[EE + e] & (NN - 1);
        int s = ei[e] & (NN - 1);
        int p = atomicAdd(&g_ints[I_POS + d], 1);
        if (p >= 0 && p < EE) g_ints[I_ESRC + p] = s;
    }
}

// ---------------- generic NT GEMM: C[M,Nd] = A[M,K] @ B[Nd,K]^T + bias ----------------
// BM=128 BN=64 BK=16, 256 threads, 8x4 microtile. EPI: 0 none, 1 exact GELU.
template <int EPI>
__global__ void k_gemm(const float* __restrict__ A, const float* __restrict__ B,
                       const float* __restrict__ bias, float* __restrict__ Cm,
                       int M, int Nd, int K) {
    __shared__ float As[16][132];
    __shared__ float Bs[16][68];
    int tid = threadIdx.x;
    int tx = tid & 15, ty = tid >> 4;
    int bm = blockIdx.y * 128, bn = blockIdx.x * 64;
    float acc[8][4];
#pragma unroll
    for (int i = 0; i < 8; i++)
#pragma unroll
        for (int j = 0; j < 4; j++) acc[i][j] = 0.f;

    for (int k0 = 0; k0 < K; k0 += 16) {
#pragma unroll
        for (int i = 0; i < 2; i++) {
            int f = tid + i * 256;           // 512 float4s -> 128x16
            int m = f >> 2;
            int kq = (f & 3) * 4;
            float4 v = *(const float4*)&A[(long)(bm + m) * K + k0 + kq];
            As[kq + 0][m] = v.x; As[kq + 1][m] = v.y;
            As[kq + 2][m] = v.z; As[kq + 3][m] = v.w;
        }
        {
            int f = tid;                     // 256 float4s -> 64x16
            int n = f >> 2;
            int kq = (f & 3) * 4;
            float4 v = *(const float4*)&B[(long)(bn + n) * K + k0 + kq];
            Bs[kq + 0][n] = v.x; Bs[kq + 1][n] = v.y;
            Bs[kq + 2][n] = v.z; Bs[kq + 3][n] = v.w;
        }
        __syncthreads();
#pragma unroll
        for (int k = 0; k < 16; k++) {
            float4 a0 = *(const float4*)&As[k][ty * 8];
            float4 a1 = *(const float4*)&As[k][ty * 8 + 4];
            float4 b0 = *(const float4*)&Bs[k][tx * 4];
            float a[8] = {a0.x, a0.y, a0.z, a0.w, a1.x, a1.y, a1.z, a1.w};
            float b[4] = {b0.x, b0.y, b0.z, b0.w};
#pragma unroll
            for (int i = 0; i < 8; i++)
#pragma unroll
                for (int j = 0; j < 4; j++) acc[i][j] += a[i] * b[j];
        }
        __syncthreads();
    }
#pragma unroll
    for (int i = 0; i < 8; i++) {
        long m = bm + ty * 8 + i;
#pragma unroll
        for (int j = 0; j < 4; j++) {
            int n = bn + tx * 4 + j;
            float v = acc[i][j] + bias[n];
            if (EPI == 1) v = 0.5f * v * (1.f + erff(v * 0.70710678118654752f));
            Cm[m * Nd + n] = v;
        }
    }
}

// ---------------- GAT per-node online softmax aggregation ----------------
// grid = NN blocks, 256 threads (8 warps = 8 heads)
__global__ void k_gat(const float* __restrict__ xl, const float* __restrict__ xr,
                      const float* __restrict__ att, const float* __restrict__ gbias,
                      float* __restrict__ outp) {
    int i = blockIdx.x;
    int w = threadIdx.x >> 5;      // head
    int lane = threadIdx.x & 31;
    int c0 = lane, c1 = lane + 32;
    const float* xli = xl + (long)i * CC + w * COH;
    float xl0 = xli[c0], xl1 = xli[c1];
    float a0 = att[w * COH + c0], a1 = att[w * COH + c1];
    float m = -1e30f, l = 0.f, acc0 = 0.f, acc1 = 0.f;
    int beg = g_ints[I_OFF + i], end = g_ints[I_OFF + i + 1];
    for (int j = beg; j <= end; j++) {
        int s = (j < end) ? g_ints[I_ESRC + j] : i;   // append self loop
        const float* xrs = xr + (long)s * CC + w * COH;
        float xr0 = xrs[c0], xr1 = xrs[c1];
        float e0 = xl0 + xr0; e0 = (e0 > 0.f) ? e0 : 0.2f * e0;
        float e1 = xl1 + xr1; e1 = (e1 > 0.f) ? e1 : 0.2f * e1;
        float p = e0 * a0 + e1 * a1;
#pragma unroll
        for (int o = 16; o; o >>= 1) p += __shfl_xor_sync(0xffffffffu, p, o);
        float mn = fmaxf(m, p);
        float sc = __expf(m - mn);
        float wg = __expf(p - mn);
        l = l * sc + wg;
        acc0 = acc0 * sc + xr0 * wg;
        acc1 = acc1 * sc + xr1 * wg;
        m = mn;
    }
    float inv = 1.f / l;
    outp[(long)i * CC + w * COH + c0] = acc0 * inv + gbias[w * COH + c0];
    outp[(long)i * CC + w * COH + c1] = acc1 * inv + gbias[w * COH + c1];
}

// ---------------- residual add + layernorm ----------------
__global__ void k_add_ln(const float* __restrict__ x, const float* __restrict__ h,
                         const float* __restrict__ g, const float* __restrict__ b,
                         float* __restrict__ outp) {
    int row = blockIdx.x;
    int t = threadIdx.x;           // 256
    __shared__ float sh[8];
    float v0 = x[(long)row * CC + t]       + h[(long)row * CC + t];
    float v1 = x[(long)row * CC + 256 + t] + h[(long)row * CC + 256 + t];
    float s = v0 + v1;
#pragma unroll
    for (int o = 16; o; o >>= 1) s += __shfl_xor_sync(0xffffffffu, s, o);
    if ((t & 31) == 0) sh[t >> 5] = s;
    __syncthreads();
    float tot = 0.f;
#pragma unroll
    for (int i = 0; i < 8; i++) tot += sh[i];
    float mu = tot * (1.f / 512.f);
    __syncthreads();
    float d0 = v0 - mu, d1 = v1 - mu;
    float q = d0 * d0 + d1 * d1;
#pragma unroll
    for (int o = 16; o; o >>= 1) q += __shfl_xor_sync(0xffffffffu, q, o);
    if ((t & 31) == 0) sh[t >> 5] = q;
    __syncthreads();
    float var = 0.f;
#pragma unroll
    for (int i = 0; i < 8; i++) var += sh[i];
    var *= (1.f / 512.f);
    float rstd = rsqrtf(var + 1e-5f);
    outp[(long)row * CC + t]       = d0 * rstd * g[t]       + b[t];
    outp[(long)row * CC + 256 + t] = d1 * rstd * g[t + 256] + b[t + 256];
}

// ---------------- flash attention (fp32, 64x64 tiles) ----------------
// grid (N/64, H), 256 threads; dynamic smem: Qt,Kt,Vs,Ps each [64][68]
__global__ void k_flash(const float* __restrict__ qkv, float* __restrict__ outp) {
    extern __shared__ float sm[];
    float (*Qt)[68] = (float(*)[68])(sm);
    float (*Kt)[68] = (float(*)[68])(sm + 64 * 68);
    float (*Vs)[68] = (float(*)[68])(sm + 2 * 64 * 68);
    float (*Ps)[68] = (float(*)[68])(sm + 3 * 64 * 68);
    int h = blockIdx.y;
    int q0 = blockIdx.x * 64;
    int tid = threadIdx.x;
    int tx = tid & 15, ty = tid >> 4;

    for (int idx = tid; idx < 64 * 64; idx += 256) {
        int r = idx >> 6, d = idx & 63;
        Qt[d][r] = qkv[(long)(q0 + r) * QKVW + h * COH + d] * 0.125f;
    }
    float m[4], l[4], o[4][4];
#pragma unroll
    for (int i = 0; i < 4; i++) {
        m[i] = -1e30f; l[i] = 0.f;
#pragma unroll
        for (int j = 0; j < 4; j++) o[i][j] = 0.f;
    }
    for (int kv0 = 0; kv0 < NN; kv0 += 64) {
        __syncthreads();
        for (int idx = tid; idx < 64 * 64; idx += 256) {
            int r = idx >> 6, d = idx & 63;
            long base = (long)(kv0 + r) * QKVW + h * COH + d;
            Kt[d][r] = qkv[base + CC];
            Vs[r][d] = qkv[base + 2 * CC];
        }
        __syncthreads();
        float s[4][4];
#pragma unroll
        for (int i = 0; i < 4; i++)
#pragma unroll
            for (int j = 0; j < 4; j++) s[i][j] = 0.f;
#pragma unroll 8
        for (int d = 0; d < 64; d++) {
            float4 qa = *(const float4*)&Qt[d][ty * 4];
            float4 kb = *(const float4*)&Kt[d][tx * 4];
            float qv[4] = {qa.x, qa.y, qa.z, qa.w};
            float kv[4] = {kb.x, kb.y, kb.z, kb.w};
#pragma unroll
            for (int i = 0; i < 4; i++)
#pragma unroll
                for (int j = 0; j < 4; j++) s[i][j] += qv[i] * kv[j];
        }
#pragma unroll
        for (int i = 0; i < 4; i++) {
            float rm = fmaxf(fmaxf(s[i][0], s[i][1]), fmaxf(s[i][2], s[i][3]));
#pragma unroll
            for (int off = 1; off < 16; off <<= 1)
                rm = fmaxf(rm, __shfl_xor_sync(0xffffffffu, rm, off));
            float mn = fmaxf(m[i], rm);
            float sc = __expf(m[i] - mn);
            float rs = 0.f;
#pragma unroll
            for (int j = 0; j < 4; j++) { s[i][j] = __expf(s[i][j] - mn); rs += s[i][j]; }
#pragma unroll
            for (int off = 1; off < 16; off <<= 1)
                rs += __shfl_xor_sync(0xffffffffu, rs, off);
            l[i] = l[i] * sc + rs;
#pragma unroll
            for (int j = 0; j < 4; j++) o[i][j] *= sc;
            m[i] = mn;
#pragma unroll
            for (int j = 0; j < 4; j++) Ps[tx * 4 + j][ty * 4 + i] = s[i][j];
        }
        __syncthreads();
#pragma unroll 8
        for (int j = 0; j < 64; j++) {
            float4 pv = *(const float4*)&Ps[j][ty * 4];
            float4 vv = *(const float4*)&Vs[j][tx * 4];
            float pr[4] = {pv.x, pv.y, pv.z, pv.w};
            float vr[4] = {vv.x, vv.y, vv.z, vv.w};
#pragma unroll
            for (int i = 0; i < 4; i++)
#pragma unroll
                for (int c = 0; c < 4; c++) o[i][c] += pr[i] * vr[c];
        }
    }
#pragma unroll
    for (int i = 0; i < 4; i++) {
        float inv = 1.f / l[i];
#pragma unroll
        for (int j = 0; j < 4; j++)
            outp[(long)(q0 + ty * 4 + i) * CC + h * COH + tx * 4 + j] = o[i][j] * inv;
    }
}

// ---------------- launch ----------------
extern "C" void kernel_launch(void* const* d_in, const int* in_sizes, int n_in,
                              void* d_out, int out_size) {
    const float*      x      = (const float*)d_in[0];
    const int*        ei     = (const int*)d_in[1];     // int32 [2, E]
    const float*      gat_wl = (const float*)d_in[2];
    const float*      gat_bl = (const float*)d_in[3];
    const float*      gat_wr = (const float*)d_in[4];
    const float*      gat_br = (const float*)d_in[5];
    const float*      gat_at = (const float*)d_in[6];
    const float*      gat_b  = (const float*)d_in[7];
    const float*      in_w   = (const float*)d_in[8];
    const float*      in_b   = (const float*)d_in[9];
    const float*      out_w  = (const float*)d_in[10];
    const float*      out_b  = (const float*)d_in[11];
    const float*      ln1_g  = (const float*)d_in[12];
    const float*      ln1_b  = (const float*)d_in[13];
    const float*      ln2_g  = (const float*)d_in[14];
    const float*      ln2_b  = (const float*)d_in[15];
    const float*      ln3_g  = (const float*)d_in[16];
    const float*      ln3_b  = (const float*)d_in[17];
    const float*      w1     = (const float*)d_in[18];
    const float*      b1     = (const float*)d_in[19];
    const float*      w2     = (const float*)d_in[20];
    const float*      b2     = (const float*)d_in[21];
    float* outp = (float*)d_out;

    float* gs = nullptr;
    cudaGetSymbolAddress((void**)&gs, g_scratch);

    int flash_smem = 4 * 64 * 68 * 4;
    cudaFuncSetAttribute(k_flash, cudaFuncAttributeMaxDynamicSharedMemorySize, flash_smem);

    // CSR build
    k_zero_deg<<<16, 256>>>();
    k_count<<<EE / 256, 256>>>(ei);
    k_scan<<<1, 1024>>>();
    k_scatter<<<EE / 256, 256>>>(ei);

    // GAT projections
    dim3 g512(CC / 64, NN / 128);
    k_gemm<0><<<g512, 256>>>(x, gat_wl, gat_bl, gs + S_XL, NN, CC, CC);
    k_gemm<0><<<g512, 256>>>(x, gat_wr, gat_br, gs + S_XR, NN, CC, CC);

    // GAT aggregation -> HB
    k_gat<<<NN, 256>>>(gs + S_XL, gs + S_XR, gat_at, gat_b, gs + S_HB);

    // x1 = LN(x + h_local)
    k_add_ln<<<NN, 256>>>(x, gs + S_HB, ln1_g, ln1_b, gs + S_X1);

    // QKV
    dim3 gqkv(QKVW / 64, NN / 128);
    k_gemm<0><<<gqkv, 256>>>(gs + S_X1, in_w, in_b, gs + S_QKV, NN, QKVW, CC);

    // flash attention -> ATT
    dim3 gfl(NN / 64, HH);
    k_flash<<<gfl, 256, flash_smem>>>(gs + S_QKV, gs + S_ATT);

    // out proj -> HB
    k_gemm<0><<<g512, 256>>>(gs + S_ATT, out_w, out_b, gs + S_HB, NN, CC, CC);

    // x2 = LN(x1 + h_global)
    k_add_ln<<<NN, 256>>>(gs + S_X1, gs + S_HB, ln2_g, ln2_b, gs + S_X2);

    // FFN
    dim3 gffn1(4 * CC / 64, NN / 128);
    k_gemm<1><<<gffn1, 256>>>(gs + S_X2, w1, b1, gs + S_FFN, NN, 4 * CC, CC);
    k_gemm<0><<<g512, 256>>>(gs + S_FFN, w2, b2, gs + S_HB, NN, CC, 4 * CC);

    // out = LN(x2 + ffn)
    k_add_ln<<<NN, 256>>>(gs + S_X2, gs + S_HB, ln3_g, ln3_b, outp);
}

// round 4
// speedup vs baseline: 2.0841x; 2.0841x over previous
#include <cuda_runtime.h>
#include <cuda_bf16.h>
#include <math.h>

#define NN    4096
#define CC    512
#define HH    8
#define COH   64
#define EE    131072
#define QKVW  1536

// ---------------- scratch ----------------
#define S_XL   0L
#define S_XR   (S_XL  + (long)NN*CC)
#define S_HB   (S_XR  + (long)NN*CC)
#define S_X1   (S_HB  + (long)NN*CC)
#define S_QKV  (S_X1  + (long)NN*CC)
#define S_ATT  (S_QKV + (long)NN*3*CC)
#define S_X2   (S_ATT + (long)NN*CC)
#define S_FFN  (S_X2  + (long)NN*CC)
#define S_TOT  (S_FFN + (long)NN*4*CC)

__device__ float g_scratch[S_TOT];

#define I_DEG  0
#define I_OFF  4096
#define I_POS  (I_OFF + 4097)
#define I_ESRC (I_POS + 4096)
__device__ int g_ints[I_ESRC + EE];

// ---------------- helpers ----------------
__device__ __forceinline__ void split2(float x0, float x1, unsigned &hi, unsigned &lo) {
    __nv_bfloat16 h0 = __float2bfloat16(x0);
    __nv_bfloat16 h1 = __float2bfloat16(x1);
    float r0 = x0 - __bfloat162float(h0);
    float r1 = x1 - __bfloat162float(h1);
    __nv_bfloat16 l0 = __float2bfloat16(r0);
    __nv_bfloat16 l1 = __float2bfloat16(r1);
    hi = ((unsigned)__bfloat16_as_ushort(h1) << 16) | (unsigned)__bfloat16_as_ushort(h0);
    lo = ((unsigned)__bfloat16_as_ushort(l1) << 16) | (unsigned)__bfloat16_as_ushort(l0);
}

__device__ __forceinline__ void splitS(float x, unsigned short &hi, unsigned short &lo) {
    __nv_bfloat16 h = __float2bfloat16(x);
    float r = x - __bfloat162float(h);
    __nv_bfloat16 l = __float2bfloat16(r);
    hi = __bfloat16_as_ushort(h);
    lo = __bfloat16_as_ushort(l);
}

__device__ __forceinline__ void mma16816(float* c, const unsigned* a, const unsigned* b) {
    asm volatile(
        "mma.sync.aligned.m16n8k16.row.col.f32.bf16.bf16.f32 "
        "{%0,%1,%2,%3}, {%4,%5,%6,%7}, {%8,%9}, {%0,%1,%2,%3};\n"
        : "+f"(c[0]), "+f"(c[1]), "+f"(c[2]), "+f"(c[3])
        : "r"(a[0]), "r"(a[1]), "r"(a[2]), "r"(a[3]), "r"(b[0]), "r"(b[1]));
}

// ---------------- CSR build (edge_index int32 [2,E]) ----------------
__global__ void k_zero_deg() {
    int i = blockIdx.x * blockDim.x + threadIdx.x;
    if (i < NN) g_ints[I_DEG + i] = 0;
}

__global__ void k_count(const int* __restrict__ ei) {
    int e = blockIdx.x * blockDim.x + threadIdx.x;
    if (e < EE) atomicAdd(&g_ints[I_DEG + (ei[EE + e] & (NN - 1))], 1);
}

__global__ void k_scan() {
    __shared__ int ws[32];
    int t = threadIdx.x;
    int v[4]; int tot = 0;
#pragma unroll
    for (int j = 0; j < 4; j++) { v[j] = g_ints[I_DEG + t*4 + j]; tot += v[j]; }
    int lane = t & 31, wid = t >> 5;
    int sc = tot;
#pragma unroll
    for (int o = 1; o < 32; o <<= 1) {
        int y = __shfl_up_sync(0xffffffffu, sc, o);
        if (lane >= o) sc += y;
    }
    if (lane == 31) ws[wid] = sc;
    __syncthreads();
    if (wid == 0) {
        int z = ws[lane];
#pragma unroll
        for (int o = 1; o < 32; o <<= 1) {
            int y = __shfl_up_sync(0xffffffffu, z, o);
            if (lane >= o) z += y;
        }
        ws[lane] = z;
    }
    __syncthreads();
    int excl = sc - tot + (wid ? ws[wid - 1] : 0);
    int run = excl;
#pragma unroll
    for (int j = 0; j < 4; j++) {
        g_ints[I_OFF + t*4 + j] = run;
        g_ints[I_POS + t*4 + j] = run;
        run += v[j];
    }
    if (t == 1023) g_ints[I_OFF + 4096] = run;
}

__global__ void k_scatter(const int* __restrict__ ei) {
    int e = blockIdx.x * blockDim.x + threadIdx.x;
    if (e < EE) {
        int d = ei[EE + e] & (NN - 1);
        int s = ei[e] & (NN - 1);
        int p = atomicAdd(&g_ints[I_POS + d], 1);
        if (p >= 0 && p < EE) g_ints[I_ESRC + p] = s;
    }
}

// ---------------- tensor-core NT GEMM: C[M,Nd] = A[M,K] @ B[Nd,K]^T + bias ----------------
// BM=128 BN=64 BK=32, 256 threads = 8 warps (4 in M x 2 in N), warp tile 32x32.
// bf16 hi/lo split, 3 mma products -> ~fp32 accuracy. EPI: 0 none, 1 exact GELU.
template <int EPI>
__global__ void __launch_bounds__(256) k_gemm(const float* __restrict__ A,
                                              const float* __restrict__ B,
                                              const float* __restrict__ bias,
                                              float* __restrict__ Cm,
                                              int M, int Nd, int K) {
    // row stride 20 uints (= 40 bf16 = BK 32 + pad 8): conflict-free frag loads
    __shared__ unsigned Ahs[128 * 20], Als[128 * 20];
    __shared__ unsigned Bhs[64 * 20],  Bls[64 * 20];

    int tid = threadIdx.x;
    int lane = tid & 31, wid = tid >> 5;
    int wm = wid & 3, wn = wid >> 2;
    int mBase = wm * 32, nBase = wn * 32;
    int g = lane >> 2, t = lane & 3;
    int bm = blockIdx.y * 128, bn = blockIdx.x * 64;

    float c[2][4][4];
#pragma unroll
    for (int mi = 0; mi < 2; mi++)
#pragma unroll
        for (int ni = 0; ni < 4; ni++)
#pragma unroll
            for (int j = 0; j < 4; j++) c[mi][ni][j] = 0.f;

    int lrow = tid >> 2;
    int kc = (tid & 3) * 8;      // 8 floats per thread chunk

    for (int k0 = 0; k0 < K; k0 += 32) {
        // ---- load A tile (128x32) ----
#pragma unroll
        for (int rep = 0; rep < 2; rep++) {
            int row = lrow + rep * 64;
            const float* src = &A[(long)(bm + row) * K + k0 + kc];
            float4 v0 = *(const float4*)src;
            float4 v1 = *(const float4*)(src + 4);
            unsigned h0,l0,h1,l1,h2,l2,h3,l3;
            split2(v0.x, v0.y, h0, l0); split2(v0.z, v0.w, h1, l1);
            split2(v1.x, v1.y, h2, l2); split2(v1.z, v1.w, h3, l3);
            *(uint4*)&Ahs[row * 20 + (kc >> 1)] = make_uint4(h0, h1, h2, h3);
            *(uint4*)&Als[row * 20 + (kc >> 1)] = make_uint4(l0, l1, l2, l3);
        }
        // ---- load B tile (64x32) ----
        {
            int row = lrow;
            const float* src = &B[(long)(bn + row) * K + k0 + kc];
            float4 v0 = *(const float4*)src;
            float4 v1 = *(const float4*)(src + 4);
            unsigned h0,l0,h1,l1,h2,l2,h3,l3;
            split2(v0.x, v0.y, h0, l0); split2(v0.z, v0.w, h1, l1);
            split2(v1.x, v1.y, h2, l2); split2(v1.z, v1.w, h3, l3);
            *(uint4*)&Bhs[row * 20 + (kc >> 1)] = make_uint4(h0, h1, h2, h3);
            *(uint4*)&Bls[row * 20 + (kc >> 1)] = make_uint4(l0, l1, l2, l3);
        }
        __syncthreads();

#pragma unroll
        for (int ks = 0; ks < 2; ks++) {
            unsigned ah[2][4], al[2][4], bh[4][2], bl[4][2];
#pragma unroll
            for (int mi = 0; mi < 2; mi++) {
                int r0 = (mBase + mi * 16 + g) * 20 + 8 * ks + t;
                int r1 = r0 + 8 * 20;
                ah[mi][0] = Ahs[r0];     al[mi][0] = Als[r0];
                ah[mi][1] = Ahs[r1];     al[mi][1] = Als[r1];
                ah[mi][2] = Ahs[r0 + 4]; al[mi][2] = Als[r0 + 4];
                ah[mi][3] = Ahs[r1 + 4]; al[mi][3] = Als[r1 + 4];
            }
#pragma unroll
            for (int ni = 0; ni < 4; ni++) {
                int rn = (nBase + ni * 8 + g) * 20 + 8 * ks + t;
                bh[ni][0] = Bhs[rn];     bl[ni][0] = Bls[rn];
                bh[ni][1] = Bhs[rn + 4]; bl[ni][1] = Bls[rn + 4];
            }
#pragma unroll
            for (int mi = 0; mi < 2; mi++)
#pragma unroll
                for (int ni = 0; ni < 4; ni++) {
                    mma16816(c[mi][ni], al[mi], bh[ni]);
                    mma16816(c[mi][ni], ah[mi], bl[ni]);
                    mma16816(c[mi][ni], ah[mi], bh[ni]);
                }
        }
        __syncthreads();
    }

    // epilogue
#pragma unroll
    for (int mi = 0; mi < 2; mi++)
#pragma unroll
        for (int ni = 0; ni < 4; ni++)
#pragma unroll
            for (int j = 0; j < 4; j++) {
                long m = bm + mBase + mi * 16 + g + ((j >> 1) * 8);
                int n = bn + nBase + ni * 8 + 2 * t + (j & 1);
                float v = c[mi][ni][j] + bias[n];
                if (EPI == 1) v = 0.5f * v * (1.f + erff(v * 0.70710678118654752f));
                Cm[m * Nd + n] = v;
            }
}

// ---------------- GAT per-node online softmax aggregation ----------------
__global__ void k_gat(const float* __restrict__ xl, const float* __restrict__ xr,
                      const float* __restrict__ att, const float* __restrict__ gbias,
                      float* __restrict__ outp) {
    int i = blockIdx.x;
    int w = threadIdx.x >> 5;
    int lane = threadIdx.x & 31;
    int c0 = lane, c1 = lane + 32;
    const float* xli = xl + (long)i * CC + w * COH;
    float xl0 = xli[c0], xl1 = xli[c1];
    float a0 = att[w * COH + c0], a1 = att[w * COH + c1];
    float m = -1e30f, l = 0.f, acc0 = 0.f, acc1 = 0.f;
    int beg = g_ints[I_OFF + i], end = g_ints[I_OFF + i + 1];
    for (int j = beg; j <= end; j++) {
        int s = (j < end) ? g_ints[I_ESRC + j] : i;
        const float* xrs = xr + (long)s * CC + w * COH;
        float xr0 = xrs[c0], xr1 = xrs[c1];
        float e0 = xl0 + xr0; e0 = (e0 > 0.f) ? e0 : 0.2f * e0;
        float e1 = xl1 + xr1; e1 = (e1 > 0.f) ? e1 : 0.2f * e1;
        float p = e0 * a0 + e1 * a1;
#pragma unroll
        for (int o = 16; o; o >>= 1) p += __shfl_xor_sync(0xffffffffu, p, o);
        float mn = fmaxf(m, p);
        float sc = __expf(m - mn);
        float wg = __expf(p - mn);
        l = l * sc + wg;
        acc0 = acc0 * sc + xr0 * wg;
        acc1 = acc1 * sc + xr1 * wg;
        m = mn;
    }
    float inv = 1.f / l;
    outp[(long)i * CC + w * COH + c0] = acc0 * inv + gbias[w * COH + c0];
    outp[(long)i * CC + w * COH + c1] = acc1 * inv + gbias[w * COH + c1];
}

// ---------------- residual add + layernorm ----------------
__global__ void k_add_ln(const float* __restrict__ x, const float* __restrict__ h,
                         const float* __restrict__ g, const float* __restrict__ b,
                         float* __restrict__ outp) {
    int row = blockIdx.x;
    int t = threadIdx.x;
    __shared__ float sh[8];
    float v0 = x[(long)row * CC + t]       + h[(long)row * CC + t];
    float v1 = x[(long)row * CC + 256 + t] + h[(long)row * CC + 256 + t];
    float s = v0 + v1;
#pragma unroll
    for (int o = 16; o; o >>= 1) s += __shfl_xor_sync(0xffffffffu, s, o);
    if ((t & 31) == 0) sh[t >> 5] = s;
    __syncthreads();
    float tot = 0.f;
#pragma unroll
    for (int i = 0; i < 8; i++) tot += sh[i];
    float mu = tot * (1.f / 512.f);
    __syncthreads();
    float d0 = v0 - mu, d1 = v1 - mu;
    float q = d0 * d0 + d1 * d1;
#pragma unroll
    for (int o = 16; o; o >>= 1) q += __shfl_xor_sync(0xffffffffu, q, o);
    if ((t & 31) == 0) sh[t >> 5] = q;
    __syncthreads();
    float var = 0.f;
#pragma unroll
    for (int i = 0; i < 8; i++) var += sh[i];
    var *= (1.f / 512.f);
    float rstd = rsqrtf(var + 1e-5f);
    outp[(long)row * CC + t]       = d0 * rstd * g[t]       + b[t];
    outp[(long)row * CC + 256 + t] = d1 * rstd * g[t + 256] + b[t + 256];
}

// ---------------- flash attention, tensor cores (bf16 split) ----------------
// grid (N/64, H), 128 threads = 4 warps; each warp: 16 q-rows x full 64 cols.
// smem layout (uint units, row stride 36 uints = 72 bf16):
//   Qh 0, Ql 2304, Kh 4608, Kl 6912, Vh 9216 (transposed: [d][kv]), Vl 11520
#define FQH 0
#define FQL 2304
#define FKH 4608
#define FKL 6912
#define FVH 9216
#define FVL 11520
#define FLASH_SMEM (13824 * 4)

__global__ void __launch_bounds__(128) k_flash(const float* __restrict__ qkv,
                                               float* __restrict__ outp) {
    extern __shared__ unsigned sm[];
    int h = blockIdx.y;
    int q0 = blockIdx.x * 64;
    int tid = threadIdx.x;
    int lane = tid & 31, wid = tid >> 5;
    int g = lane >> 2, t = lane & 3;
    int mBase = wid * 16;
    const float qs = 0.125f * 1.44269504088896f;   // 1/sqrt(64) * log2(e)

    // load+split Q (64 rows x 64 d)
#pragma unroll
    for (int i = 0; i < 4; i++) {
        int cchunk = tid + i * 128;        // 512 chunks of 8 floats
        int r = cchunk >> 3;
        int kc = (cchunk & 7) * 8;
        const float* src = &qkv[(long)(q0 + r) * QKVW + h * COH + kc];
        float4 v0 = *(const float4*)src;
        float4 v1 = *(const float4*)(src + 4);
        unsigned h0,l0,h1,l1,h2,l2,h3,l3;
        split2(v0.x * qs, v0.y * qs, h0, l0); split2(v0.z * qs, v0.w * qs, h1, l1);
        split2(v1.x * qs, v1.y * qs, h2, l2); split2(v1.z * qs, v1.w * qs, h3, l3);
        *(uint4*)&sm[FQH + r * 36 + (kc >> 1)] = make_uint4(h0, h1, h2, h3);
        *(uint4*)&sm[FQL + r * 36 + (kc >> 1)] = make_uint4(l0, l1, l2, l3);
    }

    float m0 = -1e30f, m1 = -1e30f, l0s = 0.f, l1s = 0.f;
    float o[8][4];
#pragma unroll
    for (int nd = 0; nd < 8; nd++)
#pragma unroll
        for (int j = 0; j < 4; j++) o[nd][j] = 0.f;

    for (int kv0 = 0; kv0 < NN; kv0 += 64) {
        __syncthreads();
        // K tile (64x64) split
#pragma unroll
        for (int i = 0; i < 4; i++) {
            int cchunk = tid + i * 128;
            int r = cchunk >> 3;
            int kc = (cchunk & 7) * 8;
            const float* src = &qkv[(long)(kv0 + r) * QKVW + CC + h * COH + kc];
            float4 v0 = *(const float4*)src;
            float4 v1 = *(const float4*)(src + 4);
            unsigned h0,l0,h1,l1,h2,l2,h3,l3;
            split2(v0.x, v0.y, h0, l0); split2(v0.z, v0.w, h1, l1);
            split2(v1.x, v1.y, h2, l2); split2(v1.z, v1.w, h3, l3);
            *(uint4*)&sm[FKH + r * 36 + (kc >> 1)] = make_uint4(h0, h1, h2, h3);
            *(uint4*)&sm[FKL + r * 36 + (kc >> 1)] = make_uint4(l0, l1, l2, l3);
        }
        // V tile transposed: Vh[d][kv]
        {
            unsigned short* Vhu = (unsigned short*)&sm[FVH];
            unsigned short* Vlu = (unsigned short*)&sm[FVL];
            int r = tid >> 1;
            int dbase = (tid & 1) * 32;
            const float* src = &qkv[(long)(kv0 + r) * QKVW + 2 * CC + h * COH + dbase];
#pragma unroll
            for (int q4 = 0; q4 < 8; q4++) {
                float4 v = *(const float4*)(src + q4 * 4);
                int d = dbase + q4 * 4;
                unsigned short hh, ll;
                splitS(v.x, hh, ll); Vhu[(d+0)*72 + r] = hh; Vlu[(d+0)*72 + r] = ll;
                splitS(v.y, hh, ll); Vhu[(d+1)*72 + r] = hh; Vlu[(d+1)*72 + r] = ll;
                splitS(v.z, hh, ll); Vhu[(d+2)*72 + r] = hh; Vlu[(d+2)*72 + r] = ll;
                splitS(v.w, hh, ll); Vhu[(d+3)*72 + r] = hh; Vlu[(d+3)*72 + r] = ll;
            }
        }
        __syncthreads();

        // ---- S = Q K^T (warp: 16 rows x 64 cols) ----
        float s[8][4];
#pragma unroll
        for (int ni = 0; ni < 8; ni++)
#pragma unroll
            for (int j = 0; j < 4; j++) s[ni][j] = 0.f;

#pragma unroll
        for (int ks = 0; ks < 4; ks++) {
            unsigned ah[4], al[4];
            int r0 = (mBase + g) * 36 + 8 * ks + t;
            int r1 = r0 + 8 * 36;
            ah[0] = sm[FQH + r0];     al[0] = sm[FQL + r0];
            ah[1] = sm[FQH + r1];     al[1] = sm[FQL + r1];
            ah[2] = sm[FQH + r0 + 4]; al[2] = sm[FQL + r0 + 4];
            ah[3] = sm[FQH + r1 + 4]; al[3] = sm[FQL + r1 + 4];
#pragma unroll
            for (int ni = 0; ni < 8; ni++) {
                int rn = (ni * 8 + g) * 36 + 8 * ks + t;
                unsigned bh[2], bl[2];
                bh[0] = sm[FKH + rn];     bl[0] = sm[FKL + rn];
                bh[1] = sm[FKH + rn + 4]; bl[1] = sm[FKL + rn + 4];
                mma16816(s[ni], al, bh);
                mma16816(s[ni], ah, bl);
                mma16816(s[ni], ah, bh);
            }
        }

        // ---- online softmax (base-2) ----
        float mx0 = -1e30f, mx1 = -1e30f;
#pragma unroll
        for (int ni = 0; ni < 8; ni++) {
            mx0 = fmaxf(mx0, fmaxf(s[ni][0], s[ni][1]));
            mx1 = fmaxf(mx1, fmaxf(s[ni][2], s[ni][3]));
        }
        mx0 = fmaxf(mx0, __shfl_xor_sync(0xffffffffu, mx0, 1));
        mx0 = fmaxf(mx0, __shfl_xor_sync(0xffffffffu, mx0, 2));
        mx1 = fmaxf(mx1, __shfl_xor_sync(0xffffffffu, mx1, 1));
        mx1 = fmaxf(mx1, __shfl_xor_sync(0xffffffffu, mx1, 2));
        float mn0 = fmaxf(m0, mx0), mn1 = fmaxf(m1, mx1);
        float sc0 = exp2f(m0 - mn0), sc1 = exp2f(m1 - mn1);
        m0 = mn0; m1 = mn1;
        float sum0 = 0.f, sum1 = 0.f;
#pragma unroll
        for (int ni = 0; ni < 8; ni++) {
            s[ni][0] = exp2f(s[ni][0] - m0); sum0 += s[ni][0];
            s[ni][1] = exp2f(s[ni][1] - m0); sum0 += s[ni][1];
            s[ni][2] = exp2f(s[ni][2] - m1); sum1 += s[ni][2];
            s[ni][3] = exp2f(s[ni][3] - m1); sum1 += s[ni][3];
        }
        sum0 += __shfl_xor_sync(0xffffffffu, sum0, 1);
        sum0 += __shfl_xor_sync(0xffffffffu, sum0, 2);
        sum1 += __shfl_xor_sync(0xffffffffu, sum1, 1);
        sum1 += __shfl_xor_sync(0xffffffffu, sum1, 2);
        l0s = l0s * sc0 + sum0;
        l1s = l1s * sc1 + sum1;
#pragma unroll
        for (int nd = 0; nd < 8; nd++) {
            o[nd][0] *= sc0; o[nd][1] *= sc0;
            o[nd][2] *= sc1; o[nd][3] *= sc1;
        }

        // ---- O += P V : P fragments packed straight from score regs ----
#pragma unroll
        for (int ks = 0; ks < 4; ks++) {
            unsigned ph[4], pl[4];
            split2(s[2*ks][0],   s[2*ks][1],   ph[0], pl[0]);
            split2(s[2*ks][2],   s[2*ks][3],   ph[1], pl[1]);
            split2(s[2*ks+1][0], s[2*ks+1][1], ph[2], pl[2]);
            split2(s[2*ks+1][2], s[2*ks+1][3], ph[3], pl[3]);
#pragma unroll
            for (int nd = 0; nd < 8; nd++) {
                int rn = (nd * 8 + g) * 36 + 8 * ks + t;
                unsigned bh[2], bl[2];
                bh[0] = sm[FVH + rn];     bl[0] = sm[FVL + rn];
                bh[1] = sm[FVH + rn + 4]; bl[1] = sm[FVL + rn + 4];
                mma16816(o[nd], pl, bh);
                mma16816(o[nd], ph, bl);
                mma16816(o[nd], ph, bh);
            }
        }
    }

    float inv0 = 1.f / l0s, inv1 = 1.f / l1s;
#pragma unroll
    for (int nd = 0; nd < 8; nd++) {
        int ccol = h * COH + nd * 8 + 2 * t;
        long r0 = q0 + mBase + g;
        outp[r0 * CC + ccol]           = o[nd][0] * inv0;
        outp[r0 * CC + ccol + 1]       = o[nd][1] * inv0;
        outp[(r0 + 8) * CC + ccol]     = o[nd][2] * inv1;
        outp[(r0 + 8) * CC + ccol + 1] = o[nd][3] * inv1;
    }
}

// ---------------- launch ----------------
extern "C" void kernel_launch(void* const* d_in, const int* in_sizes, int n_in,
                              void* d_out, int out_size) {
    const float* x      = (const float*)d_in[0];
    const int*   ei     = (const int*)d_in[1];
    const float* gat_wl = (const float*)d_in[2];
    const float* gat_bl = (const float*)d_in[3];
    const float* gat_wr = (const float*)d_in[4];
    const float* gat_br = (const float*)d_in[5];
    const float* gat_at = (const float*)d_in[6];
    const float* gat_b  = (const float*)d_in[7];
    const float* in_w   = (const float*)d_in[8];
    const float* in_b   = (const float*)d_in[9];
    const float* out_w  = (const float*)d_in[10];
    const float* out_b  = (const float*)d_in[11];
    const float* ln1_g  = (const float*)d_in[12];
    const float* ln1_b  = (const float*)d_in[13];
    const float* ln2_g  = (const float*)d_in[14];
    const float* ln2_b  = (const float*)d_in[15];
    const float* ln3_g  = (const float*)d_in[16];
    const float* ln3_b  = (const float*)d_in[17];
    const float* w1     = (const float*)d_in[18];
    const float* b1     = (const float*)d_in[19];
    const float* w2     = (const float*)d_in[20];
    const float* b2     = (const float*)d_in[21];
    float* outp = (float*)d_out;

    float* gs = nullptr;
    cudaGetSymbolAddress((void**)&gs, g_scratch);

    cudaFuncSetAttribute(k_flash, cudaFuncAttributeMaxDynamicSharedMemorySize, FLASH_SMEM);

    // CSR build
    k_zero_deg<<<16, 256>>>();
    k_count<<<EE / 256, 256>>>(ei);
    k_scan<<<1, 1024>>>();
    k_scatter<<<EE / 256, 256>>>(ei);

    // GAT projections
    dim3 g512(CC / 64, NN / 128);
    k_gemm<0><<<g512, 256>>>(x, gat_wl, gat_bl, gs + S_XL, NN, CC, CC);
    k_gemm<0><<<g512, 256>>>(x, gat_wr, gat_br, gs + S_XR, NN, CC, CC);

    // GAT aggregation
    k_gat<<<NN, 256>>>(gs + S_XL, gs + S_XR, gat_at, gat_b, gs + S_HB);

    // x1 = LN(x + h_local)
    k_add_ln<<<NN, 256>>>(x, gs + S_HB, ln1_g, ln1_b, gs + S_X1);

    // QKV
    dim3 gqkv(QKVW / 64, NN / 128);
    k_gemm<0><<<gqkv, 256>>>(gs + S_X1, in_w, in_b, gs + S_QKV, NN, QKVW, CC);

    // flash attention
    dim3 gfl(NN / 64, HH);
    k_flash<<<gfl, 128, FLASH_SMEM>>>(gs + S_QKV, gs + S_ATT);

    // out proj
    k_gemm<0><<<g512, 256>>>(gs + S_ATT, out_w, out_b, gs + S_HB, NN, CC, CC);

    // x2 = LN(x1 + h_global)
    k_add_ln<<<NN, 256>>>(gs + S_X1, gs + S_HB, ln2_g, ln2_b, gs + S_X2);

    // FFN
    dim3 gffn1(4 * CC / 64, NN / 128);
    k_gemm<1><<<gffn1, 256>>>(gs + S_X2, w1, b1, gs + S_FFN, NN, 4 * CC, CC);
    k_gemm<0><<<g512, 256>>>(gs + S_FFN, w2, b2, gs + S_HB, NN, CC, 4 * CC);

    // out = LN(x2 + ffn)
    k_add_ln<<<NN, 256>>>(gs + S_X2, gs + S_HB, ln3_g, ln3_b, outp);
}